// round 13
// baseline (speedup 1.0000x reference)
#include <cuda_runtime.h>
#include <cuda_fp16.h>
#include <cstdint>
#include <math.h>

// Causal attention, B=4, S=4096, D=64, fp32 in/out.
// out = [ attn_vec (B*S*64) | attn_weights (B*S*S) ]
// Single-kernel design: fp16 mma.m16n8k16 + ldmatrix; normalization fused via
// per-(b,qt) counters. cnt1 = rowsums ready; cnt2 = vec partials flushed.
// Diagonal CTA writes the normalized attn_vec rows (no finalize kernel).

constexpr int Bb = 4;
constexpr int Ss = 4096;
constexpr int Dh = 64;
constexpr int BQ = 128;
constexpr int BK = 128;
constexpr int NT = Ss / BQ;          // 32

// u32-word offsets in dynamic smem
constexpr int OFFW_Q  = 0;           // Qh [128][64] halves, pitch 32 words
constexpr int OFFW_K  = 4096;        // Kh [128][64] halves, pitch 32 words
constexpr int OFFW_P  = 0;           // Ph [128][128] halves, pitch 64 words (overlays Q+K)
constexpr int OFFW_V  = 8192;        // Vt [64][128] halves (d-major), pitch 64 words
constexpr int OFFW_VA = 12288;       // vacc fp32 [128][64] staging (separate from P!)
constexpr int SMEM_WORDS = 20480;
constexpr int SMEM_BYTES = SMEM_WORDS * 4;   // 81920

__device__ float g_rsum[Bb * Ss];
__device__ float g_vec [Bb * Ss * Dh];
__device__ int   g_cnt [Bb * NT];
__device__ int   g_cnt2[Bb * NT];

__device__ __forceinline__ unsigned packh2(float lo, float hi) {
    __half2 h = __floats2half2_rn(lo, hi);
    return *(unsigned*)&h;
}

__device__ __forceinline__ void mma16(float& c0, float& c1, float& c2, float& c3,
                                      unsigned a0, unsigned a1, unsigned a2, unsigned a3,
                                      unsigned b0, unsigned b1) {
    asm("mma.sync.aligned.m16n8k16.row.col.f32.f16.f16.f32 "
        "{%0,%1,%2,%3}, {%4,%5,%6,%7}, {%8,%9}, {%0,%1,%2,%3};"
        : "+f"(c0), "+f"(c1), "+f"(c2), "+f"(c3)
        : "r"(a0), "r"(a1), "r"(a2), "r"(a3), "r"(b0), "r"(b1));
}

__device__ __forceinline__ void ldsm4(unsigned& r0, unsigned& r1,
                                      unsigned& r2, unsigned& r3, unsigned addr) {
    asm volatile("ldmatrix.sync.aligned.m8n8.x4.shared.b16 {%0,%1,%2,%3}, [%4];"
                 : "=r"(r0), "=r"(r1), "=r"(r2), "=r"(r3) : "r"(addr));
}

__device__ __forceinline__ void stcs4(float* p, float4 v) {
    __stcs((float4*)p, v);
}

__global__ __launch_bounds__(256, 2)
void attn_score(const float* __restrict__ Q, const float* __restrict__ K,
                const float* __restrict__ V,
                float* __restrict__ out_vec, float* __restrict__ out_w)
{
    extern __shared__ __align__(16) unsigned smu[];
    __half* smh = (__half*)smu;

    const int b  = blockIdx.y;
    const int x  = blockIdx.x;
    const int qt = x >> 5;
    const int kt = x & (NT - 1);
    const int q0 = qt * BQ, k0 = kt * BK;
    const int tid = threadIdx.x;

    if (kt > qt) {
        // strictly-upper tile: pure zero-fill of the weights region, then exit
        float* wg = out_w + ((size_t)(b * Ss + q0)) * Ss + k0;
        const float4 z = make_float4(0.f, 0.f, 0.f, 0.f);
        #pragma unroll
        for (int i = 0; i < 16; i++) {
            const int idx = tid + i * 256;
            const int row = idx >> 5;
            const int c4  = (idx & 31) << 2;
            stcs4(wg + (size_t)row * Ss + c4, z);
        }
        return;
    }

    // ---- stage Q, K (fp16, swizzled, pitch 32 words) ----
    const float* Qg = Q + ((size_t)(b * Ss + q0)) * Dh;
    const float* Kg = K + ((size_t)(b * Ss + k0)) * Dh;
    const float* Vg = V + ((size_t)(b * Ss + k0)) * Dh;
    #pragma unroll
    for (int i = 0; i < 8; i++) {
        const int idx = tid + i * 256;
        const int row = idx >> 4;
        const int c4  = (idx & 15) << 2;
        const int w0  = c4 >> 1;
        const int swr = (row & 7) << 2;
        const int bw  = row * 32 + (w0 ^ swr);

        float4 q4 = *(const float4*)(Qg + row * Dh + c4);
        *(uint2*)(smu + OFFW_Q + bw) = make_uint2(packh2(q4.x, q4.y), packh2(q4.z, q4.w));

        float4 k4 = *(const float4*)(Kg + row * Dh + c4);
        *(uint2*)(smu + OFFW_K + bw) = make_uint2(packh2(k4.x, k4.y), packh2(k4.z, k4.w));
    }
    // ---- stage V transposed: Vt[d][k] halves, pitch 64 words, swizzled ----
    #pragma unroll
    for (int i = 0; i < 8; i++) {
        const int idx = tid + i * 256;
        const int k   = idx & 127;
        const int d4  = (idx >> 7) << 2;
        float4 v4 = *(const float4*)(Vg + k * Dh + d4);
        float vv[4] = {v4.x, v4.y, v4.z, v4.w};
        #pragma unroll
        for (int j = 0; j < 4; j++) {
            const int d = d4 + j;
            const int wv = (k >> 1) ^ ((d & 7) << 2);
            smh[((OFFW_V + d * 64 + wv) << 1) + (k & 1)] = __float2half_rn(vv[j]);
        }
    }
    __syncthreads();   // staging complete

    const int w = tid >> 5, lane = tid & 31;
    const int grp = lane >> 2, tig = lane & 3;
    const int sw  = grp << 2;

    // ldmatrix lane roles
    const unsigned smb = (unsigned)__cvta_generic_to_shared(smu);
    const int lm = lane >> 3, li = lane & 7;
    const int lmA_r = (lm & 1) << 3;
    const int lmA_k = (lm >> 1) << 2;
    const int lmB_r = (lm >> 1) << 3;
    const int lmB_k = (lm & 1) << 2;

    // ---- QK^T: warp tile 64x32 (wm in {0,1}, wn in {0..3}) ----
    const int wm = w & 1, wn = w >> 1;
    float acc[4][4][4];
    #pragma unroll
    for (int i = 0; i < 4; i++)
        #pragma unroll
        for (int j = 0; j < 4; j++)
            #pragma unroll
            for (int c = 0; c < 4; c++) acc[i][j][c] = 0.0f;

    #pragma unroll
    for (int kk = 0; kk < 4; kk++) {
        unsigned ah[4][4];
        #pragma unroll
        for (int am = 0; am < 4; am++) {
            const int row = wm * 64 + am * 16 + lmA_r + li;
            const unsigned addr = smb +
                ((OFFW_Q + row * 32 + (((kk << 3) + lmA_k) ^ ((row & 7) << 2))) << 2);
            ldsm4(ah[am][0], ah[am][1], ah[am][2], ah[am][3], addr);
        }
        unsigned bh[4][2];
        #pragma unroll
        for (int g = 0; g < 2; g++) {
            const int row = wn * 32 + (g << 4) + lmB_r + li;
            const unsigned addr = smb +
                ((OFFW_K + row * 32 + (((kk << 3) + lmB_k) ^ ((row & 7) << 2))) << 2);
            ldsm4(bh[2*g][0], bh[2*g][1], bh[2*g+1][0], bh[2*g+1][1], addr);
        }
        #pragma unroll
        for (int am = 0; am < 4; am++)
            #pragma unroll
            for (int an = 0; an < 4; an++) {
                float* c = acc[am][an];
                mma16(c[0], c[1], c[2], c[3],
                      ah[am][0], ah[am][1], ah[am][2], ah[am][3],
                      bh[an][0], bh[an][1]);
            }
    }

    __syncthreads();   // QK reads of Qh/Kh done; Ph may overwrite

    // ---- mask + exp; stage fp16 P; rowsum atomics ----
    #pragma unroll
    for (int am = 0; am < 4; am++) {
        const int rl_loc = wm * 64 + am * 16 + grp;
        const int rowl = q0 + rl_loc;
        const int rowh = rowl + 8;
        float rlo = 0.0f, rhi = 0.0f;
        #pragma unroll
        for (int an = 0; an < 4; an++) {
            const int cl_loc = wn * 32 + an * 8 + 2 * tig;
            const int col = k0 + cl_loc;
            float* c = acc[am][an];
            float e0 = (col     <= rowl) ? __expf(c[0] * 0.125f) : 0.0f;
            float e1 = (col + 1 <= rowl) ? __expf(c[1] * 0.125f) : 0.0f;
            float e2 = (col     <= rowh) ? __expf(c[2] * 0.125f) : 0.0f;
            float e3 = (col + 1 <= rowh) ? __expf(c[3] * 0.125f) : 0.0f;
            rlo += e0 + e1; rhi += e2 + e3;

            const int wcol = (cl_loc >> 1) ^ sw;
            smu[OFFW_P + rl_loc * 64 + wcol]       = packh2(e0, e1);
            smu[OFFW_P + (rl_loc + 8) * 64 + wcol] = packh2(e2, e3);
        }
        rlo += __shfl_xor_sync(0xffffffffu, rlo, 1);
        rlo += __shfl_xor_sync(0xffffffffu, rlo, 2);
        rhi += __shfl_xor_sync(0xffffffffu, rhi, 1);
        rhi += __shfl_xor_sync(0xffffffffu, rhi, 2);
        if (tig == 0) {
            atomicAdd(&g_rsum[b * Ss + rowl], rlo);
            atomicAdd(&g_rsum[b * Ss + rowh], rhi);
        }
    }
    __syncthreads();   // Ph staged; all warps' rowsum atomics issued

    // publish rowsum arrival
    if (tid == 0) {
        __threadfence();
        atomicAdd(&g_cnt[b * NT + qt], 1);
    }

    // ---- PV partial: warp tile 32x32 (wm2 in {0..3}, wn2 in {0,1}) ----
    const int wm2 = w >> 1, wn2 = w & 1;
    float vacc[2][4][4];
    #pragma unroll
    for (int i = 0; i < 2; i++)
        #pragma unroll
        for (int j = 0; j < 4; j++)
            #pragma unroll
            for (int c = 0; c < 4; c++) vacc[i][j][c] = 0.0f;

    #pragma unroll
    for (int ks = 0; ks < 8; ks++) {
        unsigned pa[2][4];
        #pragma unroll
        for (int am = 0; am < 2; am++) {
            const int row = wm2 * 32 + am * 16 + lmA_r + li;
            const unsigned addr = smb +
                ((OFFW_P + row * 64 + (((ks << 3) + lmA_k) ^ ((row & 7) << 2))) << 2);
            ldsm4(pa[am][0], pa[am][1], pa[am][2], pa[am][3], addr);
        }
        unsigned vb[4][2];
        #pragma unroll
        for (int g = 0; g < 2; g++) {
            const int row = wn2 * 32 + (g << 4) + lmB_r + li;   // d index
            const unsigned addr = smb +
                ((OFFW_V + row * 64 + (((ks << 3) + lmB_k) ^ ((row & 7) << 2))) << 2);
            ldsm4(vb[2*g][0], vb[2*g][1], vb[2*g+1][0], vb[2*g+1][1], addr);
        }
        #pragma unroll
        for (int am = 0; am < 2; am++)
            #pragma unroll
            for (int an = 0; an < 4; an++) {
                float* c = vacc[am][an];
                mma16(c[0], c[1], c[2], c[3],
                      pa[am][0], pa[am][1], pa[am][2], pa[am][3],
                      vb[an][0], vb[an][1]);
            }
    }

    // ---- stage vacc to its own smem region (swizzled 8-word blocks) ----
    float* vsm = (float*)smu + OFFW_VA;   // [128][64] fp32
    #pragma unroll
    for (int am = 0; am < 2; am++) {
        const int rl = wm2 * 32 + am * 16 + grp;
        const int rh = rl + 8;
        #pragma unroll
        for (int an = 0; an < 4; an++) {
            const int d  = wn2 * 32 + an * 8 + 2 * tig;
            const int wl = d ^ (grp << 3);
            float* c = vacc[am][an];
            *(float2*)(vsm + rl * 64 + wl) = make_float2(c[0], c[1]);
            *(float2*)(vsm + rh * 64 + wl) = make_float2(c[2], c[3]);
        }
    }
    __syncthreads();

    // ---- row-coalesced atomic flush of vec partials ----
    #pragma unroll
    for (int pass = 0; pass < 8; pass++) {
        const int rloc = pass * 16 + w * 2 + (lane >> 4);
        const int f    = lane & 15;
        const int swv  = (rloc & 7) << 3;
        float* gv = g_vec + ((size_t)(b * Ss + q0 + rloc)) * Dh;
        #pragma unroll
        for (int j = 0; j < 4; j++) {
            float val = vsm[rloc * 64 + ((f + 16 * j) ^ swv)];
            atomicAdd(gv + f + 16 * j, val);
        }
    }

    // publish vec-flush arrival (rigorous: every thread fences its own REDs)
    __threadfence();
    __syncthreads();
    if (tid == 0) atomicAdd(&g_cnt2[b * NT + qt], 1);

    // ---- wait for the whole row's rowsums, then write normalized weights ----
    if (tid == 0) {
        const int target = qt + 1;
        while (atomicAdd(&g_cnt[b * NT + qt], 0) < target) __nanosleep(200);
        __threadfence();   // acquire
    }
    __syncthreads();

    #pragma unroll
    for (int pass = 0; pass < 16; pass++) {
        const int rloc = pass * 8 + w;
        const float inv = 1.0f / __ldcg(&g_rsum[b * Ss + q0 + rloc]);
        const int swp = (rloc & 7) << 2;
        uint2 pw = *(const uint2*)(smu + OFFW_P + rloc * 64 + ((2 * lane) ^ swp));
        float2 f0 = __half22float2(*(__half2*)&pw.x);
        float2 f1 = __half22float2(*(__half2*)&pw.y);
        stcs4(out_w + ((size_t)(b * Ss + q0 + rloc)) * Ss + k0 + 4 * lane,
              make_float4(f0.x * inv, f0.y * inv, f1.x * inv, f1.y * inv));
    }

    // ---- diagonal CTA: wait for row's vec partials, write normalized vec ----
    if (kt == qt) {
        if (tid == 0) {
            const int target = qt + 1;
            while (atomicAdd(&g_cnt2[b * NT + qt], 0) < target) __nanosleep(200);
            __threadfence();   // acquire
        }
        __syncthreads();

        #pragma unroll
        for (int i = 0; i < 8; i++) {
            const int idx = tid + i * 256;          // 2048 float4 slots
            const int row = idx >> 4;
            const int c4  = (idx & 15) << 2;
            const int gr  = b * Ss + q0 + row;
            const float inv = 1.0f / __ldcg(&g_rsum[gr]);
            float4 v;
            v.x = __ldcg(&g_vec[(size_t)gr * Dh + c4]);
            v.y = __ldcg(&g_vec[(size_t)gr * Dh + c4 + 1]);
            v.z = __ldcg(&g_vec[(size_t)gr * Dh + c4 + 2]);
            v.w = __ldcg(&g_vec[(size_t)gr * Dh + c4 + 3]);
            v.x *= inv; v.y *= inv; v.z *= inv; v.w *= inv;
            *(float4*)(out_vec + (size_t)gr * Dh + c4) = v;
        }
    }
}

extern "C" void kernel_launch(void* const* d_in, const int* in_sizes, int n_in,
                              void* d_out, int out_size)
{
    const float* Q = (const float*)d_in[0];
    const float* K = (const float*)d_in[1];
    const float* V = (const float*)d_in[2];

    float* out_vec = (float*)d_out;
    float* out_w   = out_vec + (size_t)Bb * Ss * Dh;

    void* p_rsum = nullptr;
    void* p_vec  = nullptr;
    void* p_cnt  = nullptr;
    void* p_cnt2 = nullptr;
    cudaGetSymbolAddress(&p_rsum, g_rsum);
    cudaGetSymbolAddress(&p_vec,  g_vec);
    cudaGetSymbolAddress(&p_cnt,  g_cnt);
    cudaGetSymbolAddress(&p_cnt2, g_cnt2);
    cudaMemsetAsync(p_rsum, 0, sizeof(float) * Bb * Ss);
    cudaMemsetAsync(p_vec,  0, sizeof(float) * Bb * Ss * Dh);
    cudaMemsetAsync(p_cnt,  0, sizeof(int) * Bb * NT);
    cudaMemsetAsync(p_cnt2, 0, sizeof(int) * Bb * NT);

    cudaFuncSetAttribute(attn_score, cudaFuncAttributeMaxDynamicSharedMemorySize,
                         SMEM_BYTES);

    dim3 gridA(NT * NT, Bb);                       // all (qt,kt); upper tiles zero-fill
    attn_score<<<gridA, 256, SMEM_BYTES>>>(Q, K, V, out_vec, out_w);
}